// round 12
// baseline (speedup 1.0000x reference)
#include <cuda_runtime.h>
#include <cuda_bf16.h>
#include <stdint.h>

#define BB 2
#define SS 2048
#define DD 1024
#define HH 16
#define DHD 64
#define MM (BB*SS)      // 4096
#define NHEAD (BB*HH)   // 32

typedef __nv_bfloat16 bf16;

// ---------------------------------------------------------------------------
// Globals: 8 bf16 planes x 8MB = 64MB (proven-safe set, unchanged).
// XH/XL hold split(x) for qkv, then attn overwrites them with split(att).
// ---------------------------------------------------------------------------
#define DEVARR __device__ __align__(16)
DEVARR bf16 XH [(size_t)MM*DD];        DEVARR bf16 XL [(size_t)MM*DD];
DEVARR bf16 QHg[(size_t)NHEAD*SS*DHD]; DEVARR bf16 QLg[(size_t)NHEAD*SS*DHD];
DEVARR bf16 KHg[(size_t)NHEAD*SS*DHD]; DEVARR bf16 KLg[(size_t)NHEAD*SS*DHD];
DEVARR bf16 VHg[(size_t)NHEAD*SS*DHD]; DEVARR bf16 VLg[(size_t)NHEAD*SS*DHD];

// ---------------------------------------------------------------------------
__device__ __forceinline__ void split_pair(float x0, float x1, uint32_t& hi, uint32_t& lo) {
    __nv_bfloat16 h0 = __float2bfloat16_rn(x0);
    __nv_bfloat16 h1 = __float2bfloat16_rn(x1);
    __nv_bfloat16 l0 = __float2bfloat16_rn(x0 - __bfloat162float(h0));
    __nv_bfloat16 l1 = __float2bfloat16_rn(x1 - __bfloat162float(h1));
    hi = ((uint32_t)__bfloat16_as_ushort(h1) << 16) | (uint32_t)__bfloat16_as_ushort(h0);
    lo = ((uint32_t)__bfloat16_as_ushort(l1) << 16) | (uint32_t)__bfloat16_as_ushort(l0);
}
__device__ __forceinline__ void mma16(float* d, const uint32_t* a, uint32_t b0, uint32_t b1) {
    asm volatile("mma.sync.aligned.m16n8k16.row.col.f32.bf16.bf16.f32 "
        "{%0,%1,%2,%3}, {%4,%5,%6,%7}, {%8,%9}, {%0,%1,%2,%3};"
        : "+f"(d[0]), "+f"(d[1]), "+f"(d[2]), "+f"(d[3])
        : "r"(a[0]), "r"(a[1]), "r"(a[2]), "r"(a[3]), "r"(b0), "r"(b1));
}

// Fragment layouts, BK=64 (kb 0..3)
#define AFI4(s,kb,wb,l,r) (((((s)*4+(kb))*8+(wb))*32+(l))*4+(r))   // 8192 words
#define BFI4(s,kb,l,i)    ((((s)*4+(kb))*32+(l))*36+(i))           // 9216 words
#define GEMM_SMEM ((8192 + 9216) * 4)   // 69632 B (dynamic, under proven 73728)

// ---------------------------------------------------------------------------
// prep: split x into hi/lo planes (one time)
// ---------------------------------------------------------------------------
__global__ __launch_bounds__(256) void splitx_kernel(const float* __restrict__ src) {
    const size_t i = ((size_t)blockIdx.x * 256 + threadIdx.x) * 4;
    const float4 v = *(const float4*)&src[i];
    uint32_t h0, l0, h1, l1;
    split_pair(v.x, v.y, h0, l0);
    split_pair(v.z, v.w, h1, l1);
    *(uint2*)&XH[i] = make_uint2(h0, h1);
    *(uint2*)&XL[i] = make_uint2(l0, l1);
}

// staging helpers (BK=64)
__device__ __forceinline__ void storeA_frag64(uint32_t* smA,
    const uint4* pah, const uint4* pal, int akb, int awb, int ag, int arh)
{
    uint32_t uh[16], ul[16];
    #pragma unroll
    for (int c = 0; c < 4; c++) { *(uint4*)&uh[c*4] = pah[c]; *(uint4*)&ul[c*4] = pal[c]; }
    #pragma unroll
    for (int c4 = 0; c4 < 8; c4++) {
        const int cc = c4*4;
        const int kb = akb*2 + (cc >> 4), ccl = cc & 15;
        const int chalf = ccl >> 3, t0 = (ccl & 7) >> 1;
        const int reg = arh + 2*chalf, ln = ag*4 + t0;
        smA[AFI4(0,kb,awb,ln,  reg)] = uh[2*c4];
        smA[AFI4(0,kb,awb,ln+1,reg)] = uh[2*c4+1];
        smA[AFI4(1,kb,awb,ln,  reg)] = ul[2*c4];
        smA[AFI4(1,kb,awb,ln+1,reg)] = ul[2*c4+1];
    }
}
// 4 k-rows x 8 n-cols per thread: pairs (w0,w1)@tB and (w2,w3)@tB+1
__device__ __forceinline__ void storeB_frag64(uint32_t* smB,
    const float4* w,   // w[0..7]: row0{0-3,4-7}, row1{...}, row2, row3
    int ntB, int kbB, int regB, int tB)
{
    const float* w0 = (const float*)&w[0];
    const float* w1 = (const float*)&w[2];
    const float* w2 = (const float*)&w[4];
    const float* w3 = (const float*)&w[6];
    #pragma unroll
    for (int j = 0; j < 8; j++) {
        uint32_t hh, ll;
        split_pair(w0[j], w1[j], hh, ll);
        smB[BFI4(0,kbB, j*4+tB,   ntB*2+regB)] = hh;
        smB[BFI4(1,kbB, j*4+tB,   ntB*2+regB)] = ll;
        split_pair(w2[j], w3[j], hh, ll);
        smB[BFI4(0,kbB, j*4+tB+1, ntB*2+regB)] = hh;
        smB[BFI4(1,kbB, j*4+tB+1, ntB*2+regB)] = ll;
    }
}

// ---------------------------------------------------------------------------
// GEMM mainloop, BK=64: per iter
//   [LDG next 64-k chunk -> regs]  [192 MMAs]  sync  [STS next]  sync
// C[m128 x n128] = Asplit[m128 x 1024] @ B[1024 x n128]. 16 iters.
// ---------------------------------------------------------------------------
#define GEMM_BODY64(A_H, A_L, BROW_STRIDE, WSRC)                                    \
    extern __shared__ uint32_t sm[];                                                \
    uint32_t* smA = sm;                                                             \
    uint32_t* smB = sm + 8192;                                                      \
    const int tid  = threadIdx.x;                                                   \
    const int lane = tid & 31, warp = tid >> 5;                                     \
    const int ar = tid >> 1, akb = tid & 1;                                         \
    const int awb = ar >> 4, ag = ar & 7, arh = (ar >> 3) & 1;                      \
    const int kp = tid >> 4, ntB = tid & 15;                                        \
    const int kbB = kp >> 2, regB = (kp >> 1) & 1, tB = (kp & 1) * 2;               \
    const uint32_t* xh = (const uint32_t*)(A_H) + akb*16;                           \
    const uint32_t* xl = (const uint32_t*)(A_L) + akb*16;                           \
    float acc[16][4] = {};                                                          \
    uint4 pah[4], pal[4];                                                           \
    float4 wv[8];                                                                   \
    /* prime chunk 0 */                                                             \
    _Pragma("unroll")                                                               \
    for (int c = 0; c < 4; c++) {                                                   \
        pah[c] = *(const uint4*)&xh[c*4];                                           \
        pal[c] = *(const uint4*)&xl[c*4];                                           \
    }                                                                               \
    _Pragma("unroll")                                                               \
    for (int r = 0; r < 4; r++) {                                                   \
        const float* wr = WSRC + (size_t)(4*kp + r) * (BROW_STRIDE);                \
        wv[r*2]   = *(const float4*)&wr[0];                                         \
        wv[r*2+1] = *(const float4*)&wr[4];                                         \
    }                                                                               \
    storeA_frag64(smA, pah, pal, akb, awb, ag, arh);                                \
    storeB_frag64(smB, wv, ntB, kbB, regB, tB);                                     \
    __syncthreads();                                                                \
    for (int it = 0; it < 16; it++) {                                               \
        const bool more = (it + 1 < 16);                                            \
        if (more) {                                                                 \
            const int w = (it+1)*32;                                                \
            _Pragma("unroll")                                                       \
            for (int c = 0; c < 4; c++) {                                           \
                pah[c] = *(const uint4*)&xh[w + c*4];                               \
                pal[c] = *(const uint4*)&xl[w + c*4];                               \
            }                                                                       \
            _Pragma("unroll")                                                       \
            for (int r = 0; r < 4; r++) {                                           \
                const float* wr = WSRC + (size_t)((it+1)*64 + 4*kp + r) * (BROW_STRIDE); \
                wv[r*2]   = *(const float4*)&wr[0];                                 \
                wv[r*2+1] = *(const float4*)&wr[4];                                 \
            }                                                                       \
        }                                                                           \
        _Pragma("unroll")                                                           \
        for (int kb = 0; kb < 4; kb++) {                                            \
            uint32_t AH[4], AL[4];                                                  \
            *(uint4*)AH = *(const uint4*)&smA[AFI4(0,kb,warp,lane,0)];              \
            *(uint4*)AL = *(const uint4*)&smA[AFI4(1,kb,warp,lane,0)];              \
            _Pragma("unroll")                                                       \
            for (int q = 0; q < 8; q++) {                                           \
                const uint4 h4 = *(const uint4*)&smB[BFI4(0,kb,lane,4*q)];          \
                const uint4 l4 = *(const uint4*)&smB[BFI4(1,kb,lane,4*q)];          \
                mma16(acc[2*q],   AH, h4.x, h4.y);                                  \
                mma16(acc[2*q],   AH, l4.x, l4.y);                                  \
                mma16(acc[2*q],   AL, h4.x, h4.y);                                  \
                mma16(acc[2*q+1], AH, h4.z, h4.w);                                  \
                mma16(acc[2*q+1], AH, l4.z, l4.w);                                  \
                mma16(acc[2*q+1], AL, h4.z, h4.w);                                  \
            }                                                                       \
        }                                                                           \
        __syncthreads();                                                            \
        if (more) {                                                                 \
            storeA_frag64(smA, pah, pal, akb, awb, ag, arh);                        \
            storeB_frag64(smB, wv, ntB, kbB, regB, tB);                             \
        }                                                                           \
        __syncthreads();                                                            \
    }

// ---------------------------------------------------------------------------
// Kernel 1: fused QKV projection. 2 heads/block (n128). grid (32, 24), 256 thr.
// ---------------------------------------------------------------------------
__global__ __launch_bounds__(256) void qkv_kernel(
    const float* __restrict__ Wq, const float* __restrict__ Wk, const float* __restrict__ Wv,
    const float* __restrict__ bq, const float* __restrict__ bk, const float* __restrict__ bv)
{
    const int m0 = blockIdx.x * 128;
    const int which = blockIdx.y >> 3, hp = blockIdx.y & 7;
    const int h0 = 2*hp, h1 = 2*hp + 1;
    const float* Wb = (which == 0) ? Wq : (which == 1) ? Wk : Wv;
    const int ntB_pre = threadIdx.x & 15;
    const float* wsrc = Wb + (size_t)((ntB_pre < 8) ? h0 : h1) * DD * DHD + (ntB_pre & 7) * 8;

    GEMM_BODY64(XH + (size_t)(m0 + (threadIdx.x>>1)) * DD,
                XL + (size_t)(m0 + (threadIdx.x>>1)) * DD,
                DHD, wsrc)

    // epilogue: bias, scale(q), split, store planes
    const float* biasb = (which == 0) ? bq : (which == 1) ? bk : bv;
    bf16* oh = (which == 0) ? QHg : (which == 1) ? KHg : VHg;
    bf16* ol = (which == 0) ? QLg : (which == 1) ? KLg : VLg;
    const float sc = (which == 0) ? 0.125f : 1.0f;

    const int g = lane >> 2, t4 = lane & 3;
    #pragma unroll
    for (int idx = 0; idx < 16; idx++) {
        const int head = (idx < 8) ? h0 : h1;
        const int n64 = (idx & 7)*8 + 2*t4;
        const float b0 = biasb[head*DHD + n64], b1 = biasb[head*DHD + n64 + 1];
        uint32_t hi, lo;
        int m = m0 + warp*16 + g;
        size_t ridx = (((size_t)(m >> 11) * HH + head) * SS + (m & (SS-1))) * DHD + n64;
        split_pair((acc[idx][0] + b0) * sc, (acc[idx][1] + b1) * sc, hi, lo);
        *(uint32_t*)&oh[ridx] = hi; *(uint32_t*)&ol[ridx] = lo;
        m += 8;
        ridx = (((size_t)(m >> 11) * HH + head) * SS + (m & (SS-1))) * DHD + n64;
        split_pair((acc[idx][2] + b0) * sc, (acc[idx][3] + b1) * sc, hi, lo);
        *(uint32_t*)&oh[ridx] = hi; *(uint32_t*)&ol[ridx] = lo;
    }
}

// ---------------------------------------------------------------------------
// Kernel 3: output projection. n128/block. grid (32, 8), 256 thr.
// ---------------------------------------------------------------------------
__global__ __launch_bounds__(256) void out_kernel(
    const float* __restrict__ Wo, const float* __restrict__ bo, float* __restrict__ out)
{
    const int m0 = blockIdx.x * 128;
    const int n0 = blockIdx.y * 128;
    const int ntB_pre = threadIdx.x & 15;
    const float* wsrc = Wo + n0 + ntB_pre * 8;

    GEMM_BODY64(XH + (size_t)(m0 + (threadIdx.x>>1)) * DD,
                XL + (size_t)(m0 + (threadIdx.x>>1)) * DD,
                DD, wsrc)

    const int g = lane >> 2, t4 = lane & 3;
    #pragma unroll
    for (int nt = 0; nt < 16; nt++) {
        const int n = n0 + nt*8 + 2*t4;
        const float b0 = bo[n], b1 = bo[n+1];
        const int m_a = m0 + warp*16 + g, m_b = m_a + 8;
        *(float2*)&out[(size_t)m_a * DD + n] = make_float2(acc[nt][0] + b0, acc[nt][1] + b1);
        *(float2*)&out[(size_t)m_b * DD + n] = make_float2(acc[nt][2] + b0, acc[nt][3] + b1);
    }
}

// ---------------------------------------------------------------------------
// Kernel 2: flash attention (R9 VERBATIM — measured 51% tensor).
// grid (16, 16, 2), 256 thr, dyn smem 73728 B.
// ---------------------------------------------------------------------------
#define QFI(s,kb,wb,l,r) (((((s)*4+(kb))*8+(wb))*32+(l))*4+(r))   // 8192 words
#define KFI(s,kb,l,i)    ((((s)*4+(kb))*32+(l))*20+(i))           // 5120 words
#define ATT_SMEM_BYTES ((8192 + 5120 + 5120) * 4)

__global__ __launch_bounds__(256) void attn_kernel()
{
    extern __shared__ uint32_t sm[];
    uint32_t* QF = sm;
    uint32_t* KF = sm + 8192;
    uint32_t* VF = sm + 13312;

    const int tid  = threadIdx.x;
    const int lane = tid & 31, warp = tid >> 5;
    const int g = lane >> 2, t4 = lane & 3;
    const int q0 = blockIdx.x * 128;
    const int head = blockIdx.z * HH + blockIdx.y;
    const size_t hb = (size_t)head * SS;

    const int key = tid >> 2, kbK = tid & 3;
    const int gK = key & 7, ntK = key >> 3;
    const int kpV = tid >> 3, d8 = (tid & 7) * 8;
    const int kbV = kpV >> 3, regV = (kpV >> 2) & 1, tV = kpV & 3, ntV = tid & 7;

    const uint32_t* khw = (const uint32_t*)(KHg + (hb + key) * DHD) + kbK*8;
    const uint32_t* klw = (const uint32_t*)(KLg + (hb + key) * DHD) + kbK*8;
    const uint32_t* v0h = (const uint32_t*)(VHg + (hb + 2*kpV    ) * DHD) + d8/2;
    const uint32_t* v1h = (const uint32_t*)(VHg + (hb + 2*kpV + 1) * DHD) + d8/2;
    const uint32_t* v0l = (const uint32_t*)(VLg + (hb + 2*kpV    ) * DHD) + d8/2;
    const uint32_t* v1l = (const uint32_t*)(VLg + (hb + 2*kpV + 1) * DHD) + d8/2;
    const size_t krow = (size_t)64 * DHD / 2;

    uint32_t kuh[8], kul[8], va0[4], va1[4], vb0[4], vb1[4];

    {   // stage Q once
        const int r = tid >> 1, dseg = (tid & 1) * 32;
        const int wb = r >> 4, gg = r & 7, rh = (r >> 3) & 1;
        const uint32_t* qhw = (const uint32_t*)(QHg + (hb + q0 + r) * DHD) + dseg/2;
        const uint32_t* qlw = (const uint32_t*)(QLg + (hb + q0 + r) * DHD) + dseg/2;
        uint32_t uh[16], ul[16];
        #pragma unroll
        for (int c = 0; c < 4; c++) {
            *(uint4*)&uh[c*4] = *(const uint4*)&qhw[c*4];
            *(uint4*)&ul[c*4] = *(const uint4*)&qlw[c*4];
        }
        #pragma unroll
        for (int c4 = 0; c4 < 8; c4++) {
            const int d0 = dseg + c4*4;
            const int kb = d0 >> 4, cc = d0 & 15;
            const int reg = rh + 2*(cc >> 3), ln = gg*4 + ((cc & 7) >> 1);
            QF[QFI(0,kb,wb,ln,  reg)] = uh[c4*2];
            QF[QFI(0,kb,wb,ln+1,reg)] = uh[c4*2+1];
            QF[QFI(1,kb,wb,ln,  reg)] = ul[c4*2];
            QF[QFI(1,kb,wb,ln+1,reg)] = ul[c4*2+1];
        }
    }
    {   // stage KV tile 0
        *(uint4*)&kuh[0] = *(const uint4*)&khw[0];  *(uint4*)&kuh[4] = *(const uint4*)&khw[4];
        *(uint4*)&kul[0] = *(const uint4*)&klw[0];  *(uint4*)&kul[4] = *(const uint4*)&klw[4];
        *(uint4*)va0 = *(const uint4*)v0h;  *(uint4*)va1 = *(const uint4*)v1h;
        *(uint4*)vb0 = *(const uint4*)v0l;  *(uint4*)vb1 = *(const uint4*)v1l;
        #pragma unroll
        for (int c4 = 0; c4 < 4; c4++) {
            const int cc = c4*4, reg = cc >> 3, t0 = (cc & 7) >> 1;
            KF[KFI(0,kbK,gK*4+t0,  ntK*2+reg)] = kuh[c4*2];
            KF[KFI(0,kbK,gK*4+t0+1,ntK*2+reg)] = kuh[c4*2+1];
            KF[KFI(1,kbK,gK*4+t0,  ntK*2+reg)] = kul[c4*2];
            KF[KFI(1,kbK,gK*4+t0+1,ntK*2+reg)] = kul[c4*2+1];
        }
        #pragma unroll
        for (int j = 0; j < 8; j++) {
            const uint32_t sel = (j & 1) ? 0x7632u : 0x5410u;
            VF[KFI(0,kbV, j*4+tV, ntV*2+regV)] = __byte_perm(va0[j>>1], va1[j>>1], sel);
            VF[KFI(1,kbV, j*4+tV, ntV*2+regV)] = __byte_perm(vb0[j>>1], vb1[j>>1], sel);
        }
    }
    __syncthreads();

    float O[8][4] = {};
    float mx0 = -1e30f, mx1 = -1e30f, l0s = 0.f, l1s = 0.f;

    for (int kt = 0; kt < 32; kt++) {
        const bool more = (kt + 1 < 32);
        if (more) {
            const size_t off = (size_t)(kt+1) * krow;
            *(uint4*)&kuh[0] = *(const uint4*)&khw[off];  *(uint4*)&kuh[4] = *(const uint4*)&khw[off+4];
            *(uint4*)&kul[0] = *(const uint4*)&klw[off];  *(uint4*)&kul[4] = *(const uint4*)&klw[off+4];
            *(uint4*)va0 = *(const uint4*)&v0h[off];  *(uint4*)va1 = *(const uint4*)&v1h[off];
            *(uint4*)vb0 = *(const uint4*)&v0l[off];  *(uint4*)vb1 = *(const uint4*)&v1l[off];
        }

        float S[8][4] = {};
        #pragma unroll
        for (int kb = 0; kb < 4; kb++) {
            uint32_t QH[4], QL[4], kh[16], kl[16];
            *(uint4*)QH = *(const uint4*)&QF[QFI(0,kb,warp,lane,0)];
            *(uint4*)QL = *(const uint4*)&QF[QFI(1,kb,warp,lane,0)];
            #pragma unroll
            for (int q = 0; q < 4; q++) {
                *(uint4*)&kh[q*4] = *(const uint4*)&KF[KFI(0,kb,lane,q*4)];
                *(uint4*)&kl[q*4] = *(const uint4*)&KF[KFI(1,kb,lane,q*4)];
            }
            #pragma unroll
            for (int nt = 0; nt < 8; nt++) {
                mma16(S[nt], QH, kh[nt*2], kh[nt*2+1]);
                mma16(S[nt], QH, kl[nt*2], kl[nt*2+1]);
                mma16(S[nt], QL, kh[nt*2], kh[nt*2+1]);
            }
        }

        float mt0 = -1e30f, mt1 = -1e30f;
        #pragma unroll
        for (int nt = 0; nt < 8; nt++) {
            mt0 = fmaxf(mt0, fmaxf(S[nt][0], S[nt][1]));
            mt1 = fmaxf(mt1, fmaxf(S[nt][2], S[nt][3]));
        }
        #pragma unroll
        for (int off = 2; off >= 1; off >>= 1) {
            mt0 = fmaxf(mt0, __shfl_xor_sync(0xffffffffu, mt0, off));
            mt1 = fmaxf(mt1, __shfl_xor_sync(0xffffffffu, mt1, off));
        }
        const float mn0 = fmaxf(mx0, mt0), mn1 = fmaxf(mx1, mt1);
        const float c0 = __expf(mx0 - mn0), c1 = __expf(mx1 - mn1);
        float ls0 = 0.f, ls1 = 0.f;
        #pragma unroll
        for (int nt = 0; nt < 8; nt++) {
            S[nt][0] = __expf(S[nt][0] - mn0); ls0 += S[nt][0];
            S[nt][1] = __expf(S[nt][1] - mn0); ls0 += S[nt][1];
            S[nt][2] = __expf(S[nt][2] - mn1); ls1 += S[nt][2];
            S[nt][3] = __expf(S[nt][3] - mn1); ls1 += S[nt][3];
        }
        #pragma unroll
        for (int off = 2; off >= 1; off >>= 1) {
            ls0 += __shfl_xor_sync(0xffffffffu, ls0, off);
            ls1 += __shfl_xor_sync(0xffffffffu, ls1, off);
        }
        l0s = l0s * c0 + ls0;  l1s = l1s * c1 + ls1;
        mx0 = mn0;             mx1 = mn1;
        #pragma unroll
        for (int nt = 0; nt < 8; nt++) {
            O[nt][0] *= c0; O[nt][1] *= c0;
            O[nt][2] *= c1; O[nt][3] *= c1;
        }

        #pragma unroll
        for (int kb = 0; kb < 4; kb++) {
            uint32_t ph[4], pl[4], vh[16], vl[16];
            split_pair(S[2*kb  ][0], S[2*kb  ][1], ph[0], pl[0]);
            split_pair(S[2*kb  ][2], S[2*kb  ][3], ph[1], pl[1]);
            split_pair(S[2*kb+1][0], S[2*kb+1][1], ph[2], pl[2]);
            split_pair(S[2*kb+1][2], S[2*kb+1][3], ph[3], pl[3]);
            #pragma unroll
            for (int q = 0; q < 4; q++) {
                *(uint4*)&vh[q*4] = *(const uint4*)&VF[KFI(0,kb,lane,q*4)];
                *(uint4*)&vl[q*4] = *(const uint4*)&VF[KFI(1,kb,lane,q*4)];
            }
            #pragma unroll
            for (int nt = 0; nt < 8; nt++) {
                mma16(O[nt], ph, vh[nt*2], vh[nt*2+1]);
                mma16(O[nt], ph, vl[nt*2], vl[nt*2+1]);
                mma16(O[nt], pl, vh[nt*2], vh[nt*2+1]);
            }
        }
        __syncthreads();
        if (more) {
            #pragma unroll
            for (int c4 = 0; c4 < 4; c4++) {
                const int cc = c4*4, reg = cc >> 3, t0 = (cc & 7) >> 1;
                KF[KFI(0,kbK,gK*4+t0,  ntK*2+reg)] = kuh[c4*2];
                KF[KFI(0,kbK,gK*4+t0+1,ntK*2+reg)] = kuh[c4*2+1];
                KF[KFI(1,kbK,gK*4+t0,  ntK*2+reg)] = kul[c4*2];
                KF[KFI(1,kbK,gK*4+t0+1,ntK*2+reg)] = kul[c4*2+1];
            }
            #pragma unroll
            for (int j = 0; j < 8; j++) {
                const uint32_t sel = (j & 1) ? 0x7632u : 0x5410u;
                VF[KFI(0,kbV, j*4+tV, ntV*2+regV)] = __byte_perm(va0[j>>1], va1[j>>1], sel);
                VF[KFI(1,kbV, j*4+tV, ntV*2+regV)] = __byte_perm(vb0[j>>1], vb1[j>>1], sel);
            }
        }
        __syncthreads();
    }

    const float i0 = 1.f / l0s, i1 = 1.f / l1s;
    #pragma unroll
    for (int nt = 0; nt < 8; nt++) {
        const int n = nt*8 + 2*t4;
        const int sa = q0 + warp*16 + g, sb = sa + 8;
        const size_t ia = ((size_t)blockIdx.z * SS + sa) * DD + blockIdx.y * DHD + n;
        const size_t ib = ((size_t)blockIdx.z * SS + sb) * DD + blockIdx.y * DHD + n;
        uint32_t hi, lo;
        split_pair(O[nt][0]*i0, O[nt][1]*i0, hi, lo);
        *(uint32_t*)&XH[ia] = hi; *(uint32_t*)&XL[ia] = lo;
        split_pair(O[nt][2]*i1, O[nt][3]*i1, hi, lo);
        *(uint32_t*)&XH[ib] = hi; *(uint32_t*)&XL[ib] = lo;
    }
}

// ---------------------------------------------------------------------------
extern "C" void kernel_launch(void* const* d_in, const int* in_sizes, int n_in,
                              void* d_out, int out_size)
{
    (void)in_sizes; (void)n_in; (void)out_size;
    const float* x  = (const float*)d_in[0];
    const float* Wq = (const float*)d_in[1];
    const float* Wk = (const float*)d_in[2];
    const float* Wv = (const float*)d_in[3];
    const float* bq = (const float*)d_in[4];
    const float* bk = (const float*)d_in[5];
    const float* bv = (const float*)d_in[6];
    const float* Wo = (const float*)d_in[7];
    const float* bo = (const float*)d_in[8];
    float* out = (float*)d_out;

    (void)cudaFuncSetAttribute(qkv_kernel,  cudaFuncAttributeMaxDynamicSharedMemorySize, GEMM_SMEM);
    (void)cudaFuncSetAttribute(out_kernel,  cudaFuncAttributeMaxDynamicSharedMemorySize, GEMM_SMEM);
    (void)cudaFuncSetAttribute(attn_kernel, cudaFuncAttributeMaxDynamicSharedMemorySize, ATT_SMEM_BYTES);

    splitx_kernel<<<(MM*DD)/1024, 256>>>(x);
    qkv_kernel<<<dim3(MM/128, 24), 256, GEMM_SMEM>>>(Wq, Wk, Wv, bq, bk, bv);
    attn_kernel<<<dim3(SS/128, HH, BB), 256, ATT_SMEM_BYTES>>>();
    out_kernel<<<dim3(MM/128, DD/128), 256, GEMM_SMEM>>>(Wo, bo, out);
}

// round 13
// speedup vs baseline: 1.0656x; 1.0656x over previous
#include <cuda_runtime.h>
#include <cuda_bf16.h>
#include <stdint.h>

#define BB 2
#define SS 2048
#define DD 1024
#define HH 16
#define DHD 64
#define MM (BB*SS)      // 4096
#define NHEAD (BB*HH)   // 32

typedef __nv_bfloat16 bf16;

// ---------------------------------------------------------------------------
// Globals: 8 bf16 planes x 8MB = 64MB (proven-safe set, unchanged).
// XH/XL hold split(x) for qkv, then attn overwrites them with split(att).
// ---------------------------------------------------------------------------
#define DEVARR __device__ __align__(16)
DEVARR bf16 XH [(size_t)MM*DD];        DEVARR bf16 XL [(size_t)MM*DD];
DEVARR bf16 QHg[(size_t)NHEAD*SS*DHD]; DEVARR bf16 QLg[(size_t)NHEAD*SS*DHD];
DEVARR bf16 KHg[(size_t)NHEAD*SS*DHD]; DEVARR bf16 KLg[(size_t)NHEAD*SS*DHD];
DEVARR bf16 VHg[(size_t)NHEAD*SS*DHD]; DEVARR bf16 VLg[(size_t)NHEAD*SS*DHD];

// ---------------------------------------------------------------------------
__device__ __forceinline__ void split_pair(float x0, float x1, uint32_t& hi, uint32_t& lo) {
    __nv_bfloat16 h0 = __float2bfloat16_rn(x0);
    __nv_bfloat16 h1 = __float2bfloat16_rn(x1);
    __nv_bfloat16 l0 = __float2bfloat16_rn(x0 - __bfloat162float(h0));
    __nv_bfloat16 l1 = __float2bfloat16_rn(x1 - __bfloat162float(h1));
    hi = ((uint32_t)__bfloat16_as_ushort(h1) << 16) | (uint32_t)__bfloat16_as_ushort(h0);
    lo = ((uint32_t)__bfloat16_as_ushort(l1) << 16) | (uint32_t)__bfloat16_as_ushort(l0);
}
__device__ __forceinline__ void mma16(float* d, const uint32_t* a, uint32_t b0, uint32_t b1) {
    asm volatile("mma.sync.aligned.m16n8k16.row.col.f32.bf16.bf16.f32 "
        "{%0,%1,%2,%3}, {%4,%5,%6,%7}, {%8,%9}, {%0,%1,%2,%3};"
        : "+f"(d[0]), "+f"(d[1]), "+f"(d[2]), "+f"(d[3])
        : "r"(a[0]), "r"(a[1]), "r"(a[2]), "r"(a[3]), "r"(b0), "r"(b1));
}

// A-frag layout, BM=64: [split][kb][wb(4)][lane][reg]  (2048 words)
#define AFI3(s,kb,wb,l,r) (((((s)*2+(kb))*4+(wb))*32+(l))*4+(r))
// B-frag layout, n128: [split][kb][lane][idx 0..31], stride 36 (4608 words)
#define BFI2(s,kb,l,i)    ((((s)*2+(kb))*32+(l))*36+(i))

// ---------------------------------------------------------------------------
// prep: split x into hi/lo planes (one time)
// ---------------------------------------------------------------------------
__global__ __launch_bounds__(256) void splitx_kernel(const float* __restrict__ src) {
    const size_t i = ((size_t)blockIdx.x * 256 + threadIdx.x) * 4;
    const float4 v = *(const float4*)&src[i];
    uint32_t h0, l0, h1, l1;
    split_pair(v.x, v.y, h0, l0);
    split_pair(v.z, v.w, h1, l1);
    *(uint2*)&XH[i] = make_uint2(h0, h1);
    *(uint2*)&XL[i] = make_uint2(l0, l1);
}

// staging helpers (BM=64, BK=32)
// A: one uint4 (4 k-pairs) per plane per thread
__device__ __forceinline__ void storeA_64(uint32_t* smA,
    uint4 ph, uint4 pl, int c8, int wb, int ag, int arh)
{
    const uint32_t uh[4] = {ph.x, ph.y, ph.z, ph.w};
    const uint32_t ul[4] = {pl.x, pl.y, pl.z, pl.w};
    #pragma unroll
    for (int p = 0; p < 4; p++) {
        const int kk = c8 + 2*p;            // k offset of this pair (even)
        const int kb = kk >> 4, ccl = kk & 15;
        const int reg = arh + 2*(ccl >> 3);
        const int ln  = ag*4 + ((ccl & 7) >> 1);
        smA[AFI3(0,kb,wb,ln,reg)] = uh[p];
        smA[AFI3(1,kb,wb,ln,reg)] = ul[p];
    }
}
// B: 2 k-rows x 8 n-cols per thread
__device__ __forceinline__ void storeB_64(uint32_t* smB,
    const float4* wv, int n8, int kbB, int regB, int tB)
{
    const float* w0 = (const float*)&wv[0];   // row 2kp
    const float* w1 = (const float*)&wv[2];   // row 2kp+1
    #pragma unroll
    for (int j = 0; j < 8; j++) {
        const int n = n8 + j, gn = n & 7, nt = n >> 3;
        uint32_t hh, ll;
        split_pair(w0[j], w1[j], hh, ll);
        smB[BFI2(0,kbB, gn*4+tB, nt*2+regB)] = hh;
        smB[BFI2(1,kbB, gn*4+tB, nt*2+regB)] = ll;
    }
}

// ---------------------------------------------------------------------------
// GEMM mainloop: C[m64 x n128] = Asplit[m64 x 1024] @ B[1024 x n128], BK=32.
// 256 thr, 8 warps: warp -> m-strip (warp>>1), n-half (warp&1). 2 blocks/SM.
// Per iter: [LDG next -> regs] [48 MMAs/warp] sync [STS next] sync. 32 iters.
// ---------------------------------------------------------------------------
#define GEMM_BODY3(A_H, A_L, BROW_STRIDE, WSRC)                                     \
    __shared__ uint32_t smA[2048];                                                  \
    __shared__ uint32_t smB[4608];                                                  \
    const int tid  = threadIdx.x;                                                   \
    const int lane = tid & 31, warp = tid >> 5;                                     \
    const int arow = tid >> 2, c8 = (tid & 3) * 8;                                  \
    const int awb = arow >> 4, ag = arow & 7, arh = (arow >> 3) & 1;                \
    const int kp = tid >> 4, n8 = (tid & 15) * 8;                                   \
    const int kbB = kp >> 3, regB = (kp >> 2) & 1, tB = kp & 3;                     \
    const int wms = warp >> 1, wnh = warp & 1;                                      \
    const uint32_t* xh = (const uint32_t*)(A_H) + c8/2;                             \
    const uint32_t* xl = (const uint32_t*)(A_L) + c8/2;                             \
    float acc[8][4] = {};                                                           \
    uint4 pah, pal;                                                                 \
    float4 wv[4];                                                                   \
    pah = *(const uint4*)&xh[0];                                                    \
    pal = *(const uint4*)&xl[0];                                                    \
    {   const float* wr = WSRC + (size_t)(2*kp) * (BROW_STRIDE);                    \
        wv[0] = *(const float4*)&wr[0];  wv[1] = *(const float4*)&wr[4];            \
        wr += (BROW_STRIDE);                                                        \
        wv[2] = *(const float4*)&wr[0];  wv[3] = *(const float4*)&wr[4]; }          \
    storeA_64(smA, pah, pal, c8, awb, ag, arh);                                     \
    storeB_64(smB, wv, n8, kbB, regB, tB);                                          \
    __syncthreads();                                                                \
    for (int it = 0; it < 32; it++) {                                               \
        const bool more = (it + 1 < 32);                                            \
        if (more) {                                                                 \
            pah = *(const uint4*)&xh[(it+1)*16];                                    \
            pal = *(const uint4*)&xl[(it+1)*16];                                    \
            const float* wr = WSRC + (size_t)((it+1)*32 + 2*kp) * (BROW_STRIDE);    \
            wv[0] = *(const float4*)&wr[0];  wv[1] = *(const float4*)&wr[4];        \
            wr += (BROW_STRIDE);                                                    \
            wv[2] = *(const float4*)&wr[0];  wv[3] = *(const float4*)&wr[4];        \
        }                                                                           \
        _Pragma("unroll")                                                           \
        for (int kb = 0; kb < 2; kb++) {                                            \
            uint32_t AH[4], AL[4];                                                  \
            *(uint4*)AH = *(const uint4*)&smA[AFI3(0,kb,wms,lane,0)];               \
            *(uint4*)AL = *(const uint4*)&smA[AFI3(1,kb,wms,lane,0)];               \
            _Pragma("unroll")                                                       \
            for (int q = 0; q < 4; q++) {                                           \
                const int bix = wnh*16 + 4*q;                                       \
                const uint4 h4 = *(const uint4*)&smB[BFI2(0,kb,lane,bix)];          \
                const uint4 l4 = *(const uint4*)&smB[BFI2(1,kb,lane,bix)];          \
                mma16(acc[2*q],   AH, h4.x, h4.y);                                  \
                mma16(acc[2*q+1], AH, h4.z, h4.w);                                  \
                mma16(acc[2*q],   AH, l4.x, l4.y);                                  \
                mma16(acc[2*q+1], AH, l4.z, l4.w);                                  \
                mma16(acc[2*q],   AL, h4.x, h4.y);                                  \
                mma16(acc[2*q+1], AL, h4.z, h4.w);                                  \
            }                                                                       \
        }                                                                           \
        __syncthreads();                                                            \
        if (more) {                                                                 \
            storeA_64(smA, pah, pal, c8, awb, ag, arh);                             \
            storeB_64(smB, wv, n8, kbB, regB, tB);                                  \
        }                                                                           \
        __syncthreads();                                                            \
    }

// ---------------------------------------------------------------------------
// Kernel 1: fused QKV projection. BM=64, 2 heads/block (n128).
// grid (64, 24), 256 thr.
// ---------------------------------------------------------------------------
__global__ __launch_bounds__(256) void qkv_kernel(
    const float* __restrict__ Wq, const float* __restrict__ Wk, const float* __restrict__ Wv,
    const float* __restrict__ bq, const float* __restrict__ bk, const float* __restrict__ bv)
{
    const int m0 = blockIdx.x * 64;
    const int which = blockIdx.y >> 3, hp = blockIdx.y & 7;
    const int h0 = 2*hp, h1 = 2*hp + 1;
    const float* Wb = (which == 0) ? Wq : (which == 1) ? Wk : Wv;
    const int n8_pre = (threadIdx.x & 15) * 8;
    const float* wsrc = Wb + (size_t)((n8_pre >= 64) ? h1 : h0) * DD * DHD + (n8_pre & 63);

    GEMM_BODY3(XH + (size_t)(m0 + (threadIdx.x>>2)) * DD,
               XL + (size_t)(m0 + (threadIdx.x>>2)) * DD,
               DHD, wsrc)

    // epilogue: bias, scale(q), split, store planes. warp covers one head.
    const float* biasb = (which == 0) ? bq : (which == 1) ? bk : bv;
    bf16* oh = (which == 0) ? QHg : (which == 1) ? KHg : VHg;
    bf16* ol = (which == 0) ? QLg : (which == 1) ? KLg : VLg;
    const float sc = (which == 0) ? 0.125f : 1.0f;
    const int head = wnh ? h1 : h0;

    const int g = lane >> 2, t4 = lane & 3;
    #pragma unroll
    for (int nt = 0; nt < 8; nt++) {
        const int n64 = nt*8 + 2*t4;
        const float b0 = biasb[head*DHD + n64], b1 = biasb[head*DHD + n64 + 1];
        uint32_t hi, lo;
        int m = m0 + wms*16 + g;
        size_t ridx = (((size_t)(m >> 11) * HH + head) * SS + (m & (SS-1))) * DHD + n64;
        split_pair((acc[nt][0] + b0) * sc, (acc[nt][1] + b1) * sc, hi, lo);
        *(uint32_t*)&oh[ridx] = hi; *(uint32_t*)&ol[ridx] = lo;
        m += 8;
        ridx = (((size_t)(m >> 11) * HH + head) * SS + (m & (SS-1))) * DHD + n64;
        split_pair((acc[nt][2] + b0) * sc, (acc[nt][3] + b1) * sc, hi, lo);
        *(uint32_t*)&oh[ridx] = hi; *(uint32_t*)&ol[ridx] = lo;
    }
}

// ---------------------------------------------------------------------------
// Kernel 3: output projection. BM=64, n128/block. grid (64, 8), 256 thr.
// ---------------------------------------------------------------------------
__global__ __launch_bounds__(256) void out_kernel(
    const float* __restrict__ Wo, const float* __restrict__ bo, float* __restrict__ out)
{
    const int m0 = blockIdx.x * 64;
    const int n0 = blockIdx.y * 128;
    const int n8_pre = (threadIdx.x & 15) * 8;
    const float* wsrc = Wo + n0 + n8_pre;

    GEMM_BODY3(XH + (size_t)(m0 + (threadIdx.x>>2)) * DD,
               XL + (size_t)(m0 + (threadIdx.x>>2)) * DD,
               DD, wsrc)

    const int g = lane >> 2, t4 = lane & 3;
    #pragma unroll
    for (int nt = 0; nt < 8; nt++) {
        const int n = n0 + wnh*64 + nt*8 + 2*t4;
        const float b0 = bo[n], b1 = bo[n+1];
        const int m_a = m0 + wms*16 + g, m_b = m_a + 8;
        *(float2*)&out[(size_t)m_a * DD + n] = make_float2(acc[nt][0] + b0, acc[nt][1] + b1);
        *(float2*)&out[(size_t)m_b * DD + n] = make_float2(acc[nt][2] + b0, acc[nt][3] + b1);
    }
}

// ---------------------------------------------------------------------------
// Kernel 2: flash attention (R9 VERBATIM — measured ~51% tensor).
// grid (16, 16, 2), 256 thr, dyn smem 73728 B.
// ---------------------------------------------------------------------------
#define QFI(s,kb,wb,l,r) (((((s)*4+(kb))*8+(wb))*32+(l))*4+(r))   // 8192 words
#define KFI(s,kb,l,i)    ((((s)*4+(kb))*32+(l))*20+(i))           // 5120 words
#define ATT_SMEM_BYTES ((8192 + 5120 + 5120) * 4)

__global__ __launch_bounds__(256) void attn_kernel()
{
    extern __shared__ uint32_t sm[];
    uint32_t* QF = sm;
    uint32_t* KF = sm + 8192;
    uint32_t* VF = sm + 13312;

    const int tid  = threadIdx.x;
    const int lane = tid & 31, warp = tid >> 5;
    const int g = lane >> 2, t4 = lane & 3;
    const int q0 = blockIdx.x * 128;
    const int head = blockIdx.z * HH + blockIdx.y;
    const size_t hb = (size_t)head * SS;

    const int key = tid >> 2, kbK = tid & 3;
    const int gK = key & 7, ntK = key >> 3;
    const int kpV = tid >> 3, d8 = (tid & 7) * 8;
    const int kbV = kpV >> 3, regV = (kpV >> 2) & 1, tV = kpV & 3, ntV = tid & 7;

    const uint32_t* khw = (const uint32_t*)(KHg + (hb + key) * DHD) + kbK*8;
    const uint32_t* klw = (const uint32_t*)(KLg + (hb + key) * DHD) + kbK*8;
    const uint32_t* v0h = (const uint32_t*)(VHg + (hb + 2*kpV    ) * DHD) + d8/2;
    const uint32_t* v1h = (const uint32_t*)(VHg + (hb + 2*kpV + 1) * DHD) + d8/2;
    const uint32_t* v0l = (const uint32_t*)(VLg + (hb + 2*kpV    ) * DHD) + d8/2;
    const uint32_t* v1l = (const uint32_t*)(VLg + (hb + 2*kpV + 1) * DHD) + d8/2;
    const size_t krow = (size_t)64 * DHD / 2;

    uint32_t kuh[8], kul[8], va0[4], va1[4], vb0[4], vb1[4];

    {   // stage Q once
        const int r = tid >> 1, dseg = (tid & 1) * 32;
        const int wb = r >> 4, gg = r & 7, rh = (r >> 3) & 1;
        const uint32_t* qhw = (const uint32_t*)(QHg + (hb + q0 + r) * DHD) + dseg/2;
        const uint32_t* qlw = (const uint32_t*)(QLg + (hb + q0 + r) * DHD) + dseg/2;
        uint32_t uh[16], ul[16];
        #pragma unroll
        for (int c = 0; c < 4; c++) {
            *(uint4*)&uh[c*4] = *(const uint4*)&qhw[c*4];
            *(uint4*)&ul[c*4] = *(const uint4*)&qlw[c*4];
        }
        #pragma unroll
        for (int c4 = 0; c4 < 8; c4++) {
            const int d0 = dseg + c4*4;
            const int kb = d0 >> 4, cc = d0 & 15;
            const int reg = rh + 2*(cc >> 3), ln = gg*4 + ((cc & 7) >> 1);
            QF[QFI(0,kb,wb,ln,  reg)] = uh[c4*2];
            QF[QFI(0,kb,wb,ln+1,reg)] = uh[c4*2+1];
            QF[QFI(1,kb,wb,ln,  reg)] = ul[c4*2];
            QF[QFI(1,kb,wb,ln+1,reg)] = ul[c4*2+1];
        }
    }
    {   // stage KV tile 0
        *(uint4*)&kuh[0] = *(const uint4*)&khw[0];  *(uint4*)&kuh[4] = *(const uint4*)&khw[4];
        *(uint4*)&kul[0] = *(const uint4*)&klw[0];  *(uint4*)&kul[4] = *(const uint4*)&klw[4];
        *(uint4*)va0 = *(const uint4*)v0h;  *(uint4*)va1 = *(const uint4*)v1h;
        *(uint4*)vb0 = *(const uint4*)v0l;  *(uint4*)vb1 = *(const uint4*)v1l;
        #pragma unroll
        for (int c4 = 0; c4 < 4; c4++) {
            const int cc = c4*4, reg = cc >> 3, t0 = (cc & 7) >> 1;
            KF[KFI(0,kbK,gK*4+t0,  ntK*2+reg)] = kuh[c4*2];
            KF[KFI(0,kbK,gK*4+t0+1,ntK*2+reg)] = kuh[c4*2+1];
            KF[KFI(1,kbK,gK*4+t0,  ntK*2+reg)] = kul[c4*2];
            KF[KFI(1,kbK,gK*4+t0+1,ntK*2+reg)] = kul[c4*2+1];
        }
        #pragma unroll
        for (int j = 0; j < 8; j++) {
            const uint32_t sel = (j & 1) ? 0x7632u : 0x5410u;
            VF[KFI(0,kbV, j*4+tV, ntV*2+regV)] = __byte_perm(va0[j>>1], va1[j>>1], sel);
            VF[KFI(1,kbV, j*4+tV, ntV*2+regV)] = __byte_perm(vb0[j>>1], vb1[j>>1], sel);
        }
    }
    __syncthreads();

    float O[8][4] = {};
    float mx0 = -1e30f, mx1 = -1e30f, l0s = 0.f, l1s = 0.f;

    for (int kt = 0; kt < 32; kt++) {
        const bool more = (kt + 1 < 32);
        if (more) {
            const size_t off = (size_t)(kt+1) * krow;
            *(uint4*)&kuh[0] = *(const uint4*)&khw[off];  *(uint4*)&kuh[4] = *(const uint4*)&khw[off+4];
            *(uint4*)&kul[0] = *(const uint4*)&klw[off];  *(uint4*)&kul[4] = *(const uint4*)&klw[off+4];
            *(uint4*)va0 = *(const uint4*)&v0h[off];  *(uint4*)va1 = *(const uint4*)&v1h[off];
            *(uint4*)vb0 = *(const uint4*)&v0l[off];  *(uint4*)vb1 = *(const uint4*)&v1l[off];
        }

        float S[8][4] = {};
        #pragma unroll
        for (int kb = 0; kb < 4; kb++) {
            uint32_t QH[4], QL[4], kh[16], kl[16];
            *(uint4*)QH = *(const uint4*)&QF[QFI(0,kb,warp,lane,0)];
            *(uint4*)QL = *(const uint4*)&QF[QFI(1,kb,warp,lane,0)];
            #pragma unroll
            for (int q = 0; q < 4; q++) {
                *(uint4*)&kh[q*4] = *(const uint4*)&KF[KFI(0,kb,lane,q*4)];
                *(uint4*)&kl[q*4] = *(const uint4*)&KF[KFI(1,kb,lane,q*4)];
            }
            #pragma unroll
            for (int nt = 0; nt < 8; nt++) {
                mma16(S[nt], QH, kh[nt*2], kh[nt*2+1]);
                mma16(S[nt], QH, kl[nt*2], kl[nt*2+1]);
                mma16(S[nt], QL, kh[nt*2], kh[nt*2+1]);
            }
        }

        float mt0 = -1e30f, mt1 = -1e30f;
        #pragma unroll
        for (int nt = 0; nt < 8; nt++) {
            mt0 = fmaxf(mt0, fmaxf(S[nt][0], S[nt][1]));
            mt1 = fmaxf(mt1, fmaxf(S[nt][2], S[nt][3]));
        }
        #pragma unroll
        for (int off = 2; off >= 1; off >>= 1) {
            mt0 = fmaxf(mt0, __shfl_xor_sync(0xffffffffu, mt0, off));
            mt1 = fmaxf(mt1, __shfl_xor_sync(0xffffffffu, mt1, off));
        }
        const float mn0 = fmaxf(mx0, mt0), mn1 = fmaxf(mx1, mt1);
        const float c0 = __expf(mx0 - mn0), c1 = __expf(mx1 - mn1);
        float ls0 = 0.f, ls1 = 0.f;
        #pragma unroll
        for (int nt = 0; nt < 8; nt++) {
            S[nt][0] = __expf(S[nt][0] - mn0); ls0 += S[nt][0];
            S[nt][1] = __expf(S[nt][1] - mn0); ls0 += S[nt][1];
            S[nt][2] = __expf(S[nt][2] - mn1); ls1 += S[nt][2];
            S[nt][3] = __expf(S[nt][3] - mn1); ls1 += S[nt][3];
        }
        #pragma unroll
        for (int off = 2; off >= 1; off >>= 1) {
            ls0 += __shfl_xor_sync(0xffffffffu, ls0, off);
            ls1 += __shfl_xor_sync(0xffffffffu, ls1, off);
        }
        l0s = l0s * c0 + ls0;  l1s = l1s * c1 + ls1;
        mx0 = mn0;             mx1 = mn1;
        #pragma unroll
        for (int nt = 0; nt < 8; nt++) {
            O[nt][0] *= c0; O[nt][1] *= c0;
            O[nt][2] *= c1; O[nt][3] *= c1;
        }

        #pragma unroll
        for (int kb = 0; kb < 4; kb++) {
            uint32_t ph[4], pl[4], vh[16], vl[16];
            split_pair(S[2*kb  ][0], S[2*kb  ][1], ph[0], pl[0]);
            split_pair(S[2*kb  ][2], S[2*kb  ][3], ph[1], pl[1]);
            split_pair(S[2*kb+1][0], S[2*kb+1][1], ph[2], pl[2]);
            split_pair(S[2*kb+1][2], S[2*kb+1][3], ph[3], pl[3]);
            #pragma unroll
            for (int q = 0; q < 4; q++) {
                *(uint4*)&vh[q*4] = *(const uint4*)&VF[KFI(0,kb,lane,q*4)];
                *(uint4*)&vl[q*4] = *(const uint4*)&VF[KFI(1,kb,lane,q*4)];
            }
            #pragma unroll
            for (int nt = 0; nt < 8; nt++) {
                mma16(O[nt], ph, vh[nt*2], vh[nt*2+1]);
                mma16(O[nt], ph, vl[nt*2], vl[nt*2+1]);
                mma16(O[nt], pl, vh[nt*2], vh[nt*2+1]);
            }
        }
        __syncthreads();
        if (more) {
            #pragma unroll
            for (int c4 = 0; c4 < 4; c4++) {
                const int cc = c4*4, reg = cc >> 3, t0 = (cc & 7) >> 1;
                KF[KFI(0,kbK,gK*4+t0,  ntK*2+reg)] = kuh[c4*2];
                KF[KFI(0,kbK,gK*4+t0+1,ntK*2+reg)] = kuh[c4*2+1];
                KF[KFI(1,kbK,gK*4+t0,  ntK*2+reg)] = kul[c4*2];
                KF[KFI(1,kbK,gK*4+t0+1,ntK*2+reg)] = kul[c4*2+1];
            }
            #pragma unroll
            for (int j = 0; j < 8; j++) {
                const uint32_t sel = (j & 1) ? 0x7632u : 0x5410u;
                VF[KFI(0,kbV, j*4+tV, ntV*2+regV)] = __byte_perm(va0[j>>1], va1[j>>1], sel);
                VF[KFI(1,kbV, j*4+tV, ntV*2+regV)] = __byte_perm(vb0[j>>1], vb1[j>>1], sel);
            }
        }
        __syncthreads();
    }

    const float i0 = 1.f / l0s, i1 = 1.f / l1s;
    #pragma unroll
    for (int nt = 0; nt < 8; nt++) {
        const int n = nt*8 + 2*t4;
        const int sa = q0 + warp*16 + g, sb = sa + 8;
        const size_t ia = ((size_t)blockIdx.z * SS + sa) * DD + blockIdx.y * DHD + n;
        const size_t ib = ((size_t)blockIdx.z * SS + sb) * DD + blockIdx.y * DHD + n;
        uint32_t hi, lo;
        split_pair(O[nt][0]*i0, O[nt][1]*i0, hi, lo);
        *(uint32_t*)&XH[ia] = hi; *(uint32_t*)&XL[ia] = lo;
        split_pair(O[nt][2]*i1, O[nt][3]*i1, hi, lo);
        *(uint32_t*)&XH[ib] = hi; *(uint32_t*)&XL[ib] = lo;
    }
}

// ---------------------------------------------------------------------------
extern "C" void kernel_launch(void* const* d_in, const int* in_sizes, int n_in,
                              void* d_out, int out_size)
{
    (void)in_sizes; (void)n_in; (void)out_size;
    const float* x  = (const float*)d_in[0];
    const float* Wq = (const float*)d_in[1];
    const float* Wk = (const float*)d_in[2];
    const float* Wv = (const float*)d_in[3];
    const float* bq = (const float*)d_in[4];
    const float* bk = (const float*)d_in[5];
    const float* bv = (const float*)d_in[6];
    const float* Wo = (const float*)d_in[7];
    const float* bo = (const float*)d_in[8];
    float* out = (float*)d_out;

    (void)cudaFuncSetAttribute(attn_kernel, cudaFuncAttributeMaxDynamicSharedMemorySize,
                               ATT_SMEM_BYTES);

    splitx_kernel<<<(MM*DD)/1024, 256>>>(x);
    qkv_kernel<<<dim3(MM/64, 24), 256>>>(Wq, Wk, Wv, bq, bk, bv);
    attn_kernel<<<dim3(SS/128, HH, BB), 256, ATT_SMEM_BYTES>>>();
    out_kernel<<<dim3(MM/64, DD/128), 256>>>(Wo, bo, out);
}